// round 1
// baseline (speedup 1.0000x reference)
#include <cuda_runtime.h>
#include <math.h>

#define Bdim 2
#define Hlat 128
#define Wlon 256
#define Cdim 256
#define HWsz (Hlat*Wlon)
#define MAXN 2048

// Scratch (allocation-free rule: __device__ globals)
__device__ float g_q[(size_t)Bdim*HWsz*Cdim];   // (b, h, w, c) channel-last, pre-scaled
__device__ float g_k[(size_t)Bdim*HWsz*Cdim];
__device__ float g_v[(size_t)Bdim*HWsz*Cdim];
__device__ int   g_row_off[Hlat + 2];

// ---------------------------------------------------------------------------
// Row offsets: psi_row_idx is sorted; binary-search each row boundary.
// ---------------------------------------------------------------------------
__global__ void build_row_off_kernel(const int* __restrict__ rows, int nnz) {
    int r = threadIdx.x;
    if (r > Hlat) return;
    int lo = 0, hi = nnz;
    while (lo < hi) {
        int mid = (lo + hi) >> 1;
        if (rows[mid] < r) lo = mid + 1; else hi = mid;
    }
    g_row_off[r] = lo;
}

// ---------------------------------------------------------------------------
// Fused QKV projection GEMM (fp32).
// out[j][p] = sum_c W[j][c] * x[b][c][p];  q gets *1/16 scale; + bias.
// Tiles: BM=128 positions, BN=64 out-channels, BK=16. 256 threads, 8x4 micro.
// ---------------------------------------------------------------------------
__global__ __launch_bounds__(256) void qkv_gemm_kernel(
    const float* __restrict__ x,
    const float* __restrict__ wq, const float* __restrict__ wk, const float* __restrict__ wv,
    const float* __restrict__ bq, const float* __restrict__ bk, const float* __restrict__ bv)
{
    const int BM = 128, BN = 64, BK = 16;
    __shared__ __align__(16) float As[BK][BM];
    __shared__ __align__(16) float Bs[BK][BN];

    int tid = threadIdx.x;
    int mb = blockIdx.x, nb = blockIdx.y, b = blockIdx.z;

    const float* Wm; const float* bias; float* op; float osc;
    if (nb < 4)      { Wm = wq; bias = bq; op = g_q; osc = 0.0625f; }
    else if (nb < 8) { Wm = wk; bias = bk; op = g_k; osc = 1.0f;    }
    else             { Wm = wv; bias = bv; op = g_v; osc = 1.0f;    }
    int j0 = (nb & 3) * BN;          // channel offset within the selected matrix
    int m0 = mb * BM;
    const float* xb = x + (size_t)b * Cdim * HWsz;

    float acc[8][4];
    #pragma unroll
    for (int i = 0; i < 8; ++i)
        #pragma unroll
        for (int j = 0; j < 4; ++j) acc[i][j] = 0.f;

    int tm = tid & 15;    // 16 position groups of 8
    int tn = tid >> 4;    // 16 channel groups of 4

    for (int kk = 0; kk < Cdim; kk += BK) {
        // Load X tile: 16 (c) x 128 (p), coalesced float4 along p
        #pragma unroll
        for (int pass = 0; pass < 2; ++pass) {
            int r = (tid >> 5) + pass * 8;
            int cidx = (tid & 31) * 4;
            float4 xv = *(const float4*)(xb + (size_t)(kk + r) * HWsz + m0 + cidx);
            *(float4*)&As[r][cidx] = xv;
        }
        // Load W tile: 64 (n) x 16 (k), coalesced float4 along k, store transposed
        {
            int n = tid >> 2, k4 = (tid & 3) * 4;
            float4 wvv = *(const float4*)(Wm + (size_t)(j0 + n) * Cdim + kk + k4);
            Bs[k4 + 0][n] = wvv.x; Bs[k4 + 1][n] = wvv.y;
            Bs[k4 + 2][n] = wvv.z; Bs[k4 + 3][n] = wvv.w;
        }
        __syncthreads();
        #pragma unroll
        for (int k = 0; k < BK; ++k) {
            float a[8], bb[4];
            *(float4*)&a[0] = *(const float4*)&As[k][tm * 8];
            *(float4*)&a[4] = *(const float4*)&As[k][tm * 8 + 4];
            *(float4*)&bb[0] = *(const float4*)&Bs[k][tn * 4];
            #pragma unroll
            for (int i = 0; i < 8; ++i)
                #pragma unroll
                for (int j = 0; j < 4; ++j)
                    acc[i][j] = fmaf(a[i], bb[j], acc[i][j]);
        }
        __syncthreads();
    }

    float bb0 = bias[j0 + tn * 4 + 0];
    float bb1 = bias[j0 + tn * 4 + 1];
    float bb2 = bias[j0 + tn * 4 + 2];
    float bb3 = bias[j0 + tn * 4 + 3];
    #pragma unroll
    for (int i = 0; i < 8; ++i) {
        int p = m0 + tm * 8 + i;
        float4 o;
        o.x = fmaf(acc[i][0], osc, bb0);
        o.y = fmaf(acc[i][1], osc, bb1);
        o.z = fmaf(acc[i][2], osc, bb2);
        o.w = fmaf(acc[i][3], osc, bb3);
        *(float4*)(op + ((size_t)b * HWsz + p) * Cdim + j0 + tn * 4) = o;
    }
}

// ---------------------------------------------------------------------------
// Attention: one block per output (b, ho, wo). 256 threads.
// Phase 1: warps compute logits (dot over C=256) per neighbor -> smem.
// Phase 2: block softmax (max, exp*quadweight, sum).
// Phase 3: per-channel weighted V accumulation (coalesced 1KB per neighbor).
// ---------------------------------------------------------------------------
__global__ __launch_bounds__(256) void attn_kernel(
    const float* __restrict__ qw_lat,
    const int* __restrict__ col_idx,
    float* __restrict__ out)
{
    __shared__ __align__(16) float s_q[Cdim];
    __shared__ __align__(16) float s_a[MAXN];
    __shared__ float s_red[8];
    __shared__ float s_bc[2];

    int wo = blockIdx.x, ho = blockIdx.y, b = blockIdx.z;
    int tid = threadIdx.x, lane = tid & 31, warp = tid >> 5;

    int seg = g_row_off[ho];
    int n_row = g_row_off[ho + 1] - seg;
    if (n_row > MAXN) n_row = MAXN;   // safety; real max ~1300

    s_q[tid] = g_q[(((size_t)b * Hlat + ho) * Wlon + wo) * Cdim + tid];
    __syncthreads();

    // Phase 1: logits (one neighbor per warp iteration)
    float lmax = -INFINITY;
    const float* kb = g_k + (size_t)b * Hlat * Wlon * Cdim;
    const float4* qp = (const float4*)s_q;
    float4 q0 = qp[lane * 2], q1 = qp[lane * 2 + 1];
    for (int i = warp; i < n_row; i += 8) {
        int col = col_idx[seg + i];
        int hi = col >> 8;
        int wc = ((col & 255) + wo) & 255;
        const float4* kp = (const float4*)(kb + ((size_t)(hi * Wlon + wc)) * Cdim);
        float4 k0 = kp[lane * 2], k1 = kp[lane * 2 + 1];
        float p = k0.x * q0.x;
        p = fmaf(k0.y, q0.y, p); p = fmaf(k0.z, q0.z, p); p = fmaf(k0.w, q0.w, p);
        p = fmaf(k1.x, q1.x, p); p = fmaf(k1.y, q1.y, p);
        p = fmaf(k1.z, q1.z, p); p = fmaf(k1.w, q1.w, p);
        #pragma unroll
        for (int o = 16; o > 0; o >>= 1) p += __shfl_xor_sync(0xffffffffu, p, o);
        if (lane == 0) s_a[i] = p;
        lmax = fmaxf(lmax, p);
    }
    // Block max
    #pragma unroll
    for (int o = 16; o > 0; o >>= 1) lmax = fmaxf(lmax, __shfl_xor_sync(0xffffffffu, lmax, o));
    if (lane == 0) s_red[warp] = lmax;
    __syncthreads();
    if (tid < 8) {
        float v = s_red[tid];
        #pragma unroll
        for (int o = 4; o > 0; o >>= 1) v = fmaxf(v, __shfl_xor_sync(0xffu, v, o));
        if (tid == 0) s_bc[0] = v;
    }
    __syncthreads();
    float m = s_bc[0];

    // Phase 2: alpha = exp(logit - m) * quad_weights[hi]; denom = sum
    float dloc = 0.f;
    for (int n = tid; n < n_row; n += 256) {
        int col = col_idx[seg + n];
        int hi = col >> 8;
        float a = expf(s_a[n] - m) * qw_lat[hi];
        s_a[n] = a;
        dloc += a;
    }
    #pragma unroll
    for (int o = 16; o > 0; o >>= 1) dloc += __shfl_xor_sync(0xffffffffu, dloc, o);
    if (lane == 0) s_red[warp] = dloc;
    __syncthreads();
    if (tid < 8) {
        float v = s_red[tid];
        #pragma unroll
        for (int o = 4; o > 0; o >>= 1) v += __shfl_xor_sync(0xffu, v, o);
        if (tid == 0) s_bc[1] = v;
    }
    __syncthreads();
    float inv = 1.0f / s_bc[1];

    // Phase 3: per-channel V accumulation (thread = channel)
    float accv = 0.f;
    const float* vb = g_v + (size_t)b * Hlat * Wlon * Cdim;
    for (int n = 0; n < n_row; ++n) {
        int col = col_idx[seg + n];
        int hi = col >> 8;
        int wc = ((col & 255) + wo) & 255;
        accv = fmaf(s_a[n], vb[((size_t)(hi * Wlon + wc)) * Cdim + tid], accv);
    }
    out[(((size_t)b * Cdim + tid) * Hlat + ho) * Wlon + wo] = accv * inv;
}

// ---------------------------------------------------------------------------
extern "C" void kernel_launch(void* const* d_in, const int* in_sizes, int n_in,
                              void* d_out, int out_size) {
    const float* query = (const float*)d_in[0];
    const float* wq    = (const float*)d_in[1];
    const float* wk    = (const float*)d_in[2];
    const float* wv    = (const float*)d_in[3];
    const float* bq    = (const float*)d_in[4];
    const float* bk    = (const float*)d_in[5];
    const float* bv    = (const float*)d_in[6];
    const float* qw    = (const float*)d_in[7];
    const int*   rows  = (const int*)d_in[8];
    const int*   cols  = (const int*)d_in[9];
    int nnz = in_sizes[8];
    float* out = (float*)d_out;

    build_row_off_kernel<<<1, 256>>>(rows, nnz);
    qkv_gemm_kernel<<<dim3(HWsz / 128, 12, Bdim), 256>>>(query, wq, wk, wv, bq, bk, bv);
    attn_kernel<<<dim3(Wlon, Hlat, Bdim), 256>>>(qw, cols, out);
}

// round 2
// speedup vs baseline: 1.1539x; 1.1539x over previous
#include <cuda_runtime.h>
#include <math.h>

#define Bdim 2
#define Hlat 128
#define Wlon 256
#define WPAD 260
#define Cdim 256
#define HWsz (Hlat*Wlon)
#define MAXN 2048

// Scratch (allocation-free rule: __device__ globals)
__device__ float g_q[(size_t)Bdim*HWsz*Cdim];        // (b,h,w,c)
__device__ float g_k[(size_t)Bdim*Hlat*WPAD*Cdim];   // (b,h,w,c) wrap-padded w: 0..259
__device__ float g_v[(size_t)Bdim*Hlat*WPAD*Cdim];

// ---------------------------------------------------------------------------
// Fused QKV projection GEMM (fp32).
// q -> g_q (pre-scaled by 1/16), k/v -> padded layout with w<4 duplicated.
// ---------------------------------------------------------------------------
__global__ __launch_bounds__(256) void qkv_gemm_kernel(
    const float* __restrict__ x,
    const float* __restrict__ wq, const float* __restrict__ wk, const float* __restrict__ wv,
    const float* __restrict__ bq, const float* __restrict__ bk, const float* __restrict__ bv)
{
    const int BM = 128, BN = 64, BK = 16;
    __shared__ __align__(16) float As[BK][BM];
    __shared__ __align__(16) float Bs[BK][BN];

    int tid = threadIdx.x;
    int mb = blockIdx.x, nb = blockIdx.y, b = blockIdx.z;

    const float* Wm; const float* bias; float osc; int which;
    if (nb < 4)      { Wm = wq; bias = bq; osc = 0.0625f; which = 0; }
    else if (nb < 8) { Wm = wk; bias = bk; osc = 1.0f;    which = 1; }
    else             { Wm = wv; bias = bv; osc = 1.0f;    which = 2; }
    int j0 = (nb & 3) * BN;
    int m0 = mb * BM;
    const float* xb = x + (size_t)b * Cdim * HWsz;

    float acc[8][4];
    #pragma unroll
    for (int i = 0; i < 8; ++i)
        #pragma unroll
        for (int j = 0; j < 4; ++j) acc[i][j] = 0.f;

    int tm = tid & 15;
    int tn = tid >> 4;

    for (int kk = 0; kk < Cdim; kk += BK) {
        #pragma unroll
        for (int pass = 0; pass < 2; ++pass) {
            int r = (tid >> 5) + pass * 8;
            int cidx = (tid & 31) * 4;
            float4 xv = *(const float4*)(xb + (size_t)(kk + r) * HWsz + m0 + cidx);
            *(float4*)&As[r][cidx] = xv;
        }
        {
            int n = tid >> 2, k4 = (tid & 3) * 4;
            float4 wvv = *(const float4*)(Wm + (size_t)(j0 + n) * Cdim + kk + k4);
            Bs[k4 + 0][n] = wvv.x; Bs[k4 + 1][n] = wvv.y;
            Bs[k4 + 2][n] = wvv.z; Bs[k4 + 3][n] = wvv.w;
        }
        __syncthreads();
        #pragma unroll
        for (int k = 0; k < BK; ++k) {
            float a[8], bb[4];
            *(float4*)&a[0] = *(const float4*)&As[k][tm * 8];
            *(float4*)&a[4] = *(const float4*)&As[k][tm * 8 + 4];
            *(float4*)&bb[0] = *(const float4*)&Bs[k][tn * 4];
            #pragma unroll
            for (int i = 0; i < 8; ++i)
                #pragma unroll
                for (int j = 0; j < 4; ++j)
                    acc[i][j] = fmaf(a[i], bb[j], acc[i][j]);
        }
        __syncthreads();
    }

    float bb0 = bias[j0 + tn * 4 + 0];
    float bb1 = bias[j0 + tn * 4 + 1];
    float bb2 = bias[j0 + tn * 4 + 2];
    float bb3 = bias[j0 + tn * 4 + 3];
    #pragma unroll
    for (int i = 0; i < 8; ++i) {
        int p = m0 + tm * 8 + i;
        float4 o;
        o.x = fmaf(acc[i][0], osc, bb0);
        o.y = fmaf(acc[i][1], osc, bb1);
        o.z = fmaf(acc[i][2], osc, bb2);
        o.w = fmaf(acc[i][3], osc, bb3);
        if (which == 0) {
            *(float4*)(g_q + ((size_t)b * HWsz + p) * Cdim + j0 + tn * 4) = o;
        } else {
            float* op = (which == 1) ? g_k : g_v;
            int h = p >> 8, w = p & 255;
            size_t base = (((size_t)b * Hlat + h) * WPAD + w) * Cdim + j0 + tn * 4;
            *(float4*)(op + base) = o;
            if (w < 4) *(float4*)(op + base + (size_t)Wlon * Cdim) = o;  // wrap dup
        }
    }
}

// ---------------------------------------------------------------------------
// Attention, wo-tiled T=4. One block per (b, ho, wo_tile). 256 threads.
// ---------------------------------------------------------------------------
__global__ __launch_bounds__(256) void attn_kernel(
    const float* __restrict__ qw_lat,
    const int* __restrict__ rows,
    const int* __restrict__ col_idx,
    int nnz,
    float* __restrict__ out)
{
    __shared__ __align__(16) float s_q[4][Cdim];
    __shared__ __align__(16) float s_a[MAXN * 4];
    __shared__ float s_red[32];
    __shared__ float s_m[4];
    __shared__ float s_inv[4];

    int wo0 = blockIdx.x * 4;
    int ho = blockIdx.y, b = blockIdx.z;
    int tid = threadIdx.x, lane = tid & 31, warp = tid >> 5;

    // Row segment via binary search (uniform across threads)
    int seg, n_row;
    {
        int lo = 0, hi = nnz;
        while (lo < hi) { int mid = (lo + hi) >> 1; if (rows[mid] < ho) lo = mid + 1; else hi = mid; }
        seg = lo;
        int lo2 = seg, hi2 = nnz;
        while (lo2 < hi2) { int mid = (lo2 + hi2) >> 1; if (rows[mid] < ho + 1) lo2 = mid + 1; else hi2 = mid; }
        n_row = lo2 - seg;
        if (n_row > MAXN) n_row = MAXN;
    }

    // Load 4 Q vectors into smem (wo0..wo0+3, all < 256)
    {
        int t = tid >> 6; int c4 = (tid & 63) * 4;
        const float4 v = *(const float4*)(g_q + (((size_t)b * Hlat + ho) * Wlon + wo0 + t) * Cdim + c4);
        *(float4*)&s_q[t][c4] = v;
    }
    __syncthreads();

    float4 q0[4], q1[4];
    #pragma unroll
    for (int t = 0; t < 4; ++t) {
        q0[t] = *(const float4*)&s_q[t][lane * 8];
        q1[t] = *(const float4*)&s_q[t][lane * 8 + 4];
    }

    // ---------------- Phase 1: logits ----------------
    const float* kb = g_k + (size_t)b * Hlat * WPAD * Cdim;
    float lmax = -INFINITY;   // this lane tracks t = lane&3 after the transpose-reduce
    bool b1 = (lane & 1), b2 = (lane & 2);

    for (int i = warp; i < n_row; i += 8) {
        int col = col_idx[seg + i];
        int hi = col >> 8;
        int wc = ((col & 255) + wo0) & 255;
        const float4* kp = (const float4*)(kb + ((size_t)hi * WPAD + wc) * Cdim) + lane * 2;
        float p[4];
        #pragma unroll
        for (int t = 0; t < 4; ++t) {
            float4 k0 = kp[t * (Cdim / 4)];
            float4 k1 = kp[t * (Cdim / 4) + 1];
            float s = k0.x * q0[t].x;
            s = fmaf(k0.y, q0[t].y, s); s = fmaf(k0.z, q0[t].z, s); s = fmaf(k0.w, q0[t].w, s);
            s = fmaf(k1.x, q1[t].x, s); s = fmaf(k1.y, q1[t].y, s);
            s = fmaf(k1.z, q1[t].z, s); s = fmaf(k1.w, q1[t].w, s);
            p[t] = s;
        }
        // transpose-reduce: lanes with lane&3==t end with full sum of p[t]
        float uA = b1 ? p[1] : p[0], wA = b1 ? p[0] : p[1];
        uA += __shfl_xor_sync(0xffffffffu, wA, 1);
        float uB = b1 ? p[3] : p[2], wB = b1 ? p[2] : p[3];
        uB += __shfl_xor_sync(0xffffffffu, wB, 1);
        float v = b2 ? uB : uA, x = b2 ? uA : uB;
        v += __shfl_xor_sync(0xffffffffu, x, 2);
        v += __shfl_xor_sync(0xffffffffu, v, 4);
        v += __shfl_xor_sync(0xffffffffu, v, 8);
        v += __shfl_xor_sync(0xffffffffu, v, 16);
        if (lane < 4) s_a[i * 4 + lane] = v;
        lmax = fmaxf(lmax, v);
    }
    // block max per t
    lmax = fmaxf(lmax, __shfl_xor_sync(0xffffffffu, lmax, 4));
    lmax = fmaxf(lmax, __shfl_xor_sync(0xffffffffu, lmax, 8));
    lmax = fmaxf(lmax, __shfl_xor_sync(0xffffffffu, lmax, 16));
    if (lane < 4) s_red[warp * 4 + lane] = lmax;
    __syncthreads();
    if (tid < 32) {
        float v = s_red[tid];
        v = fmaxf(v, __shfl_xor_sync(0xffffffffu, v, 4));
        v = fmaxf(v, __shfl_xor_sync(0xffffffffu, v, 8));
        v = fmaxf(v, __shfl_xor_sync(0xffffffffu, v, 16));
        if (tid < 4) s_m[tid] = v;
    }
    __syncthreads();

    // ---------------- Phase 2: alpha + denom ----------------
    float mt = s_m[tid & 3];
    float dloc = 0.f;
    for (int idx = tid; idx < n_row * 4; idx += 256) {
        int n = idx >> 2;
        int col = col_idx[seg + n];
        float a = __expf(s_a[idx] - mt) * qw_lat[col >> 8];
        s_a[idx] = a;
        dloc += a;
    }
    dloc += __shfl_xor_sync(0xffffffffu, dloc, 4);
    dloc += __shfl_xor_sync(0xffffffffu, dloc, 8);
    dloc += __shfl_xor_sync(0xffffffffu, dloc, 16);
    if (lane < 4) s_red[warp * 4 + lane] = dloc;
    __syncthreads();
    if (tid < 32) {
        float v = s_red[tid];
        v += __shfl_xor_sync(0xffffffffu, v, 4);
        v += __shfl_xor_sync(0xffffffffu, v, 8);
        v += __shfl_xor_sync(0xffffffffu, v, 16);
        if (tid < 4) s_inv[tid] = 1.0f / v;
    }
    __syncthreads();

    // ---------------- Phase 3: V accumulation ----------------
    const float* vb = g_v + (size_t)b * Hlat * WPAD * Cdim + tid;
    float acc0 = 0.f, acc1 = 0.f, acc2 = 0.f, acc3 = 0.f;
    #pragma unroll 2
    for (int n = 0; n < n_row; ++n) {
        int col = col_idx[seg + n];
        int hi = col >> 8;
        int wc = ((col & 255) + wo0) & 255;
        float4 a = *(const float4*)&s_a[n * 4];
        const float* vr = vb + ((size_t)hi * WPAD + wc) * Cdim;
        acc0 = fmaf(a.x, vr[0 * Cdim], acc0);
        acc1 = fmaf(a.y, vr[1 * Cdim], acc1);
        acc2 = fmaf(a.z, vr[2 * Cdim], acc2);
        acc3 = fmaf(a.w, vr[3 * Cdim], acc3);
    }
    float4 o;
    o.x = acc0 * s_inv[0];
    o.y = acc1 * s_inv[1];
    o.z = acc2 * s_inv[2];
    o.w = acc3 * s_inv[3];
    *(float4*)(out + (((size_t)b * Cdim + tid) * Hlat + ho) * Wlon + wo0) = o;
}

// ---------------------------------------------------------------------------
extern "C" void kernel_launch(void* const* d_in, const int* in_sizes, int n_in,
                              void* d_out, int out_size) {
    const float* query = (const float*)d_in[0];
    const float* wq    = (const float*)d_in[1];
    const float* wk    = (const float*)d_in[2];
    const float* wv    = (const float*)d_in[3];
    const float* bq    = (const float*)d_in[4];
    const float* bk    = (const float*)d_in[5];
    const float* bv    = (const float*)d_in[6];
    const float* qw    = (const float*)d_in[7];
    const int*   rows  = (const int*)d_in[8];
    const int*   cols  = (const int*)d_in[9];
    int nnz = in_sizes[8];
    float* out = (float*)d_out;

    qkv_gemm_kernel<<<dim3(HWsz / 128, 12, Bdim), 256>>>(query, wq, wk, wv, bq, bk, bv);
    attn_kernel<<<dim3(Wlon / 4, Hlat, Bdim), 256>>>(qw, rows, cols, nnz, out);
}

// round 3
// speedup vs baseline: 1.3905x; 1.2051x over previous
#include <cuda_runtime.h>
#include <math.h>

#define Bdim 2
#define Hlat 128
#define Wlon 256
#define WPAD 260
#define Cdim 256
#define HWsz (Hlat*Wlon)
#define MAXN 1536   // true max row degree is 1280 (pole rows)

// Scratch (allocation-free rule: __device__ globals)
__device__ float g_q[(size_t)Bdim*HWsz*Cdim];        // (b,h,w,c)
__device__ float g_k[(size_t)Bdim*Hlat*WPAD*Cdim];   // (b,h,w,c) wrap-padded w: 0..259
__device__ float g_v[(size_t)Bdim*Hlat*WPAD*Cdim];

// ---------------------------------------------------------------------------
// Fused QKV projection GEMM (fp32).
// ---------------------------------------------------------------------------
__global__ __launch_bounds__(256) void qkv_gemm_kernel(
    const float* __restrict__ x,
    const float* __restrict__ wq, const float* __restrict__ wk, const float* __restrict__ wv,
    const float* __restrict__ bq, const float* __restrict__ bk, const float* __restrict__ bv)
{
    const int BM = 128, BN = 64, BK = 16;
    __shared__ __align__(16) float As[BK][BM];
    __shared__ __align__(16) float Bs[BK][BN];

    int tid = threadIdx.x;
    int mb = blockIdx.x, nb = blockIdx.y, b = blockIdx.z;

    const float* Wm; const float* bias; float osc; int which;
    if (nb < 4)      { Wm = wq; bias = bq; osc = 0.0625f; which = 0; }
    else if (nb < 8) { Wm = wk; bias = bk; osc = 1.0f;    which = 1; }
    else             { Wm = wv; bias = bv; osc = 1.0f;    which = 2; }
    int j0 = (nb & 3) * BN;
    int m0 = mb * BM;
    const float* xb = x + (size_t)b * Cdim * HWsz;

    float acc[8][4];
    #pragma unroll
    for (int i = 0; i < 8; ++i)
        #pragma unroll
        for (int j = 0; j < 4; ++j) acc[i][j] = 0.f;

    int tm = tid & 15;
    int tn = tid >> 4;

    for (int kk = 0; kk < Cdim; kk += BK) {
        #pragma unroll
        for (int pass = 0; pass < 2; ++pass) {
            int r = (tid >> 5) + pass * 8;
            int cidx = (tid & 31) * 4;
            float4 xv = *(const float4*)(xb + (size_t)(kk + r) * HWsz + m0 + cidx);
            *(float4*)&As[r][cidx] = xv;
        }
        {
            int n = tid >> 2, k4 = (tid & 3) * 4;
            float4 wvv = *(const float4*)(Wm + (size_t)(j0 + n) * Cdim + kk + k4);
            Bs[k4 + 0][n] = wvv.x; Bs[k4 + 1][n] = wvv.y;
            Bs[k4 + 2][n] = wvv.z; Bs[k4 + 3][n] = wvv.w;
        }
        __syncthreads();
        #pragma unroll
        for (int k = 0; k < BK; ++k) {
            float a[8], bb[4];
            *(float4*)&a[0] = *(const float4*)&As[k][tm * 8];
            *(float4*)&a[4] = *(const float4*)&As[k][tm * 8 + 4];
            *(float4*)&bb[0] = *(const float4*)&Bs[k][tn * 4];
            #pragma unroll
            for (int i = 0; i < 8; ++i)
                #pragma unroll
                for (int j = 0; j < 4; ++j)
                    acc[i][j] = fmaf(a[i], bb[j], acc[i][j]);
        }
        __syncthreads();
    }

    float bb0 = bias[j0 + tn * 4 + 0];
    float bb1 = bias[j0 + tn * 4 + 1];
    float bb2 = bias[j0 + tn * 4 + 2];
    float bb3 = bias[j0 + tn * 4 + 3];
    #pragma unroll
    for (int i = 0; i < 8; ++i) {
        int p = m0 + tm * 8 + i;
        float4 o;
        o.x = fmaf(acc[i][0], osc, bb0);
        o.y = fmaf(acc[i][1], osc, bb1);
        o.z = fmaf(acc[i][2], osc, bb2);
        o.w = fmaf(acc[i][3], osc, bb3);
        if (which == 0) {
            *(float4*)(g_q + ((size_t)b * HWsz + p) * Cdim + j0 + tn * 4) = o;
        } else {
            float* op = (which == 1) ? g_k : g_v;
            int h = p >> 8, w = p & 255;
            size_t base = (((size_t)b * Hlat + h) * WPAD + w) * Cdim + j0 + tn * 4;
            *(float4*)(op + base) = o;
            if (w < 4) *(float4*)(op + base + (size_t)Wlon * Cdim) = o;  // wrap dup
        }
    }
}

// ---------------------------------------------------------------------------
// Attention, wo-tiled T=4, warp-split over t. One block per (b, ho, wo_tile).
// ---------------------------------------------------------------------------
__global__ __launch_bounds__(256) void attn_kernel(
    const float* __restrict__ qw_lat,
    const int* __restrict__ rows,
    const int* __restrict__ col_idx,
    int nnz,
    float* __restrict__ out)
{
    __shared__ __align__(16) float s_q[4][Cdim];
    __shared__ __align__(16) float s_a[MAXN * 4];
    __shared__ __align__(16) int   s_col[MAXN];
    __shared__ float s_red[32];
    __shared__ float s_m[4];
    __shared__ float s_inv[4];

    int wo0 = blockIdx.x * 4;
    int ho = blockIdx.y, b = blockIdx.z;
    int tid = threadIdx.x, lane = tid & 31, warp = tid >> 5;

    // Row segment via binary search (uniform across threads)
    int seg, n_row;
    {
        int lo = 0, hi = nnz;
        while (lo < hi) { int mid = (lo + hi) >> 1; if (rows[mid] < ho) lo = mid + 1; else hi = mid; }
        seg = lo;
        int lo2 = seg, hi2 = nnz;
        while (lo2 < hi2) { int mid = (lo2 + hi2) >> 1; if (rows[mid] < ho + 1) lo2 = mid + 1; else hi2 = mid; }
        n_row = lo2 - seg;
        if (n_row > MAXN) n_row = MAXN;
    }

    // Stage Q tile (4 x 256) and column indices in smem
    {
        int t = tid >> 6; int c4 = (tid & 63) * 4;
        *(float4*)&s_q[t][c4] =
            *(const float4*)(g_q + (((size_t)b * Hlat + ho) * Wlon + wo0 + t) * Cdim + c4);
    }
    for (int n = tid; n < n_row; n += 256) s_col[n] = col_idx[seg + n];
    __syncthreads();

    // ---------------- Phase 1: logits (warp w owns t = w&3) ----------------
    const int t = warp & 3;
    const float* kb = g_k + (size_t)b * Hlat * WPAD * Cdim;
    float4 qa = *(const float4*)&s_q[t][lane * 4];
    float4 qb = *(const float4*)&s_q[t][128 + lane * 4];

    float lmax = -INFINITY;
    #pragma unroll 2
    for (int i = (warp >> 2); i < n_row; i += 2) {
        int col = s_col[i];
        int hi = col >> 8;
        int wc = ((col & 255) + wo0) & 255;
        const float* kr = kb + (size_t)(hi * WPAD + wc + t) * Cdim;
        float4 k0 = *(const float4*)(kr + lane * 4);
        float4 k1 = *(const float4*)(kr + 128 + lane * 4);
        float s = k0.x * qa.x;
        s = fmaf(k0.y, qa.y, s); s = fmaf(k0.z, qa.z, s); s = fmaf(k0.w, qa.w, s);
        s = fmaf(k1.x, qb.x, s); s = fmaf(k1.y, qb.y, s);
        s = fmaf(k1.z, qb.z, s); s = fmaf(k1.w, qb.w, s);
        #pragma unroll
        for (int o = 16; o > 0; o >>= 1) s += __shfl_xor_sync(0xffffffffu, s, o);
        if (lane == 0) s_a[i * 4 + t] = s;
        lmax = fmaxf(lmax, s);
    }
    if (lane == 0) s_red[warp] = lmax;
    __syncthreads();
    if (tid < 4) s_m[tid] = fmaxf(s_red[tid], s_red[tid + 4]);
    __syncthreads();

    // ---------------- Phase 2: alpha + denom (per t) ----------------
    float mt = s_m[tid & 3];
    float dloc = 0.f;
    for (int idx = tid; idx < n_row * 4; idx += 256) {
        int col = s_col[idx >> 2];
        float a = __expf(s_a[idx] - mt) * qw_lat[col >> 8];
        s_a[idx] = a;
        dloc += a;
    }
    dloc += __shfl_xor_sync(0xffffffffu, dloc, 4);
    dloc += __shfl_xor_sync(0xffffffffu, dloc, 8);
    dloc += __shfl_xor_sync(0xffffffffu, dloc, 16);
    if (lane < 4) s_red[warp * 4 + lane] = dloc;
    __syncthreads();
    if (tid < 32) {
        float v = s_red[tid];
        v += __shfl_xor_sync(0xffffffffu, v, 4);
        v += __shfl_xor_sync(0xffffffffu, v, 8);
        v += __shfl_xor_sync(0xffffffffu, v, 16);
        if (tid < 4) s_inv[tid] = 1.0f / v;
    }
    // Rewrite s_col as precomputed spatial offsets (hi*WPAD + wc)
    for (int n = tid; n < n_row; n += 256) {
        int col = s_col[n];
        s_col[n] = (col >> 8) * WPAD + (((col & 255) + wo0) & 255);
    }
    __syncthreads();

    // ---------------- Phase 3: V accumulation ----------------
    // thread = (wo_t = tid>>6, channels c4..c4+3)
    int wo_t = tid >> 6;
    int c4 = (tid & 63) * 4;
    const float* vb = g_v + (size_t)b * Hlat * WPAD * Cdim + (size_t)wo_t * Cdim + c4;
    float4 acc = {0.f, 0.f, 0.f, 0.f};
    #pragma unroll 2
    for (int n = 0; n < n_row; ++n) {
        float a = s_a[n * 4 + wo_t];
        const float4 vv = *(const float4*)(vb + (size_t)s_col[n] * Cdim);
        acc.x = fmaf(a, vv.x, acc.x);
        acc.y = fmaf(a, vv.y, acc.y);
        acc.z = fmaf(a, vv.z, acc.z);
        acc.w = fmaf(a, vv.w, acc.w);
    }
    float inv = s_inv[wo_t];
    acc.x *= inv; acc.y *= inv; acc.z *= inv; acc.w *= inv;

    // Restage through smem for a coalesced-per-thread float4 store along wo
    __syncthreads();
    float* s_o = s_a;                       // reuse (needs 1024 floats)
    *(float4*)(s_o + wo_t * 256 + c4) = acc;
    __syncthreads();
    float4 o;
    o.x = s_o[0 * 256 + tid];
    o.y = s_o[1 * 256 + tid];
    o.z = s_o[2 * 256 + tid];
    o.w = s_o[3 * 256 + tid];
    *(float4*)(out + (((size_t)b * Cdim + tid) * Hlat + ho) * Wlon + wo0) = o;
}

// ---------------------------------------------------------------------------
extern "C" void kernel_launch(void* const* d_in, const int* in_sizes, int n_in,
                              void* d_out, int out_size) {
    const float* query = (const float*)d_in[0];
    const float* wq    = (const float*)d_in[1];
    const float* wk    = (const float*)d_in[2];
    const float* wv    = (const float*)d_in[3];
    const float* bq    = (const float*)d_in[4];
    const float* bk    = (const float*)d_in[5];
    const float* bv    = (const float*)d_in[6];
    const float* qw    = (const float*)d_in[7];
    const int*   rows  = (const int*)d_in[8];
    const int*   cols  = (const int*)d_in[9];
    int nnz = in_sizes[8];
    float* out = (float*)d_out;

    qkv_gemm_kernel<<<dim3(HWsz / 128, 12, Bdim), 256>>>(query, wq, wk, wv, bq, bk, bv);
    attn_kernel<<<dim3(Wlon / 4, Hlat, Bdim), 256>>>(qw, rows, cols, nnz, out);
}

// round 4
// speedup vs baseline: 2.5346x; 1.8228x over previous
#include <cuda_runtime.h>
#include <math.h>

#define Bdim 2
#define Hlat 128
#define Wlon 256
#define Cdim 256
#define HWsz (Hlat*Wlon)
#define MAXCOL 1536   // max distinct (hi,w) columns per ho (pole rows ~1280)

// Scratch (allocation-free rule: __device__ globals)
__device__ float g_q[(size_t)Bdim*HWsz*Cdim];   // (b,h,w,c), pre-scaled by 1/16
__device__ float g_k[(size_t)Bdim*HWsz*Cdim];
__device__ float g_v[(size_t)Bdim*HWsz*Cdim];
__device__ int   g_cnt[Hlat*Hlat];
__device__ int   g_arc[Hlat*Hlat];              // half-width a, 128=full circle, -1=empty

// ---------------------------------------------------------------------------
// Arc table precompute (exact, derived from CSR counts)
// ---------------------------------------------------------------------------
__global__ void zero_cnt_kernel() {
    g_cnt[blockIdx.x * 256 + threadIdx.x] = 0;
}
__global__ void count_kernel(const int* __restrict__ rows, const int* __restrict__ cols, int nnz) {
    int i = blockIdx.x * 256 + threadIdx.x;
    if (i >= nnz) return;
    atomicAdd(&g_cnt[rows[i] * Hlat + (cols[i] >> 8)], 1);
}
__global__ void arc_kernel() {
    int i = blockIdx.x * 256 + threadIdx.x;
    int c = g_cnt[i];
    g_arc[i] = (c == 0) ? -1 : ((c >= 256) ? 128 : ((c - 1) >> 1));
}

// ---------------------------------------------------------------------------
// Fused QKV projection GEMM (fp32). BM=128, BN=128, BK=16, 256 thr, 8x8 micro.
// ---------------------------------------------------------------------------
__global__ __launch_bounds__(256) void qkv_gemm_kernel(
    const float* __restrict__ x,
    const float* __restrict__ wq, const float* __restrict__ wk, const float* __restrict__ wv,
    const float* __restrict__ bq, const float* __restrict__ bk, const float* __restrict__ bv)
{
    const int BK = 16;
    __shared__ __align__(16) float As[BK][128];
    __shared__ __align__(16) float Bs[BK][128];

    int tid = threadIdx.x;
    int mb = blockIdx.x, nb = blockIdx.y, b = blockIdx.z;

    const float* Wm; const float* bias; float osc; float* op;
    if (nb < 2)      { Wm = wq; bias = bq; osc = 0.0625f; op = g_q; }
    else if (nb < 4) { Wm = wk; bias = bk; osc = 1.0f;    op = g_k; }
    else             { Wm = wv; bias = bv; osc = 1.0f;    op = g_v; }
    int j0 = (nb & 1) * 128;
    int m0 = mb * 128;
    const float* xb = x + (size_t)b * Cdim * HWsz;

    float acc[8][8];
    #pragma unroll
    for (int i = 0; i < 8; ++i)
        #pragma unroll
        for (int j = 0; j < 8; ++j) acc[i][j] = 0.f;

    int tm = tid & 15;
    int tn = tid >> 4;

    for (int kk = 0; kk < Cdim; kk += BK) {
        #pragma unroll
        for (int pass = 0; pass < 2; ++pass) {
            int r = (tid >> 5) + pass * 8;
            int cidx = (tid & 31) * 4;
            *(float4*)&As[r][cidx] =
                *(const float4*)(xb + (size_t)(kk + r) * HWsz + m0 + cidx);
        }
        #pragma unroll
        for (int pass = 0; pass < 2; ++pass) {
            int n = (tid >> 2) + pass * 64;
            int k4 = (tid & 3) * 4;
            float4 wvv = *(const float4*)(Wm + (size_t)(j0 + n) * Cdim + kk + k4);
            Bs[k4 + 0][n] = wvv.x; Bs[k4 + 1][n] = wvv.y;
            Bs[k4 + 2][n] = wvv.z; Bs[k4 + 3][n] = wvv.w;
        }
        __syncthreads();
        #pragma unroll
        for (int k = 0; k < BK; ++k) {
            float a[8], bb[8];
            *(float4*)&a[0]  = *(const float4*)&As[k][tm * 8];
            *(float4*)&a[4]  = *(const float4*)&As[k][tm * 8 + 4];
            *(float4*)&bb[0] = *(const float4*)&Bs[k][tn * 8];
            *(float4*)&bb[4] = *(const float4*)&Bs[k][tn * 8 + 4];
            #pragma unroll
            for (int i = 0; i < 8; ++i)
                #pragma unroll
                for (int j = 0; j < 8; ++j)
                    acc[i][j] = fmaf(a[i], bb[j], acc[i][j]);
        }
        __syncthreads();
    }

    float bv8[8];
    #pragma unroll
    for (int j = 0; j < 8; ++j) bv8[j] = bias[j0 + tn * 8 + j];
    #pragma unroll
    for (int i = 0; i < 8; ++i) {
        int p = m0 + tm * 8 + i;
        float* dst = op + ((size_t)b * HWsz + p) * Cdim + j0 + tn * 8;
        float4 o1, o2;
        o1.x = fmaf(acc[i][0], osc, bv8[0]); o1.y = fmaf(acc[i][1], osc, bv8[1]);
        o1.z = fmaf(acc[i][2], osc, bv8[2]); o1.w = fmaf(acc[i][3], osc, bv8[3]);
        o2.x = fmaf(acc[i][4], osc, bv8[4]); o2.y = fmaf(acc[i][5], osc, bv8[5]);
        o2.z = fmaf(acc[i][6], osc, bv8[6]); o2.w = fmaf(acc[i][7], osc, bv8[7]);
        *(float4*)dst = o1;
        *(float4*)(dst + 4) = o2;
    }
}

// ---------------------------------------------------------------------------
// Attention over distinct columns. Block = (b, ho, wo_tile of 4). 256 threads.
// Each distinct K/V row is loaded ONCE and serves all 4 outputs.
// ---------------------------------------------------------------------------
__global__ __launch_bounds__(256) void attn_kernel(
    const float* __restrict__ qw_lat,
    float* __restrict__ out)
{
    __shared__ __align__(16) float s_q[4][Cdim];          // 4 KB
    __shared__ __align__(16) float s_alpha[MAXCOL * 4];   // 24 KB (logits->alphas->partials)
    __shared__ __align__(16) int   s_off[MAXCOL];         // 6 KB  (hi*256 + wc)
    __shared__ __align__(16) int   s_aux[MAXCOL];         // 6 KB  ((a<<8) | dw0)
    __shared__ int   s_arcv[Hlat];
    __shared__ int   s_wid[Hlat];
    __shared__ int   s_start[Hlat + 1];
    __shared__ float s_red[32];
    __shared__ float s_m[4];
    __shared__ float s_inv[4];

    int wo0 = blockIdx.x * 4;
    int ho = blockIdx.y, b = blockIdx.z;
    int tid = threadIdx.x, lane = tid & 31, warp = tid >> 5;

    // --- Setup: widths, prefix sum, column map ---
    if (tid < Hlat) {
        int a = g_arc[ho * Hlat + tid];
        s_arcv[tid] = a;
        int w = (a < 0) ? 0 : (2 * a + 4);
        s_wid[tid] = (w > 256) ? 256 : w;
    }
    // Stage Q tile
    {
        int t = tid >> 6; int c4 = (tid & 63) * 4;
        *(float4*)&s_q[t][c4] =
            *(const float4*)(g_q + (((size_t)b * Hlat + ho) * Wlon + wo0 + t) * Cdim + c4);
    }
    __syncthreads();

    if (warp == 0) {
        int b0 = lane * 4;
        int w0 = s_wid[b0], w1 = s_wid[b0 + 1], w2 = s_wid[b0 + 2], w3 = s_wid[b0 + 3];
        int p1 = w0 + w1, p2 = p1 + w2, tot = p2 + w3;
        int inc = tot;
        #pragma unroll
        for (int o = 1; o < 32; o <<= 1) {
            int nv = __shfl_up_sync(0xffffffffu, inc, o);
            if (lane >= o) inc += nv;
        }
        int base = inc - tot;
        s_start[b0] = base; s_start[b0 + 1] = base + w0;
        s_start[b0 + 2] = base + p1; s_start[b0 + 3] = base + p2;
        if (lane == 31) s_start[Hlat] = inc;
    }
    __syncthreads();
    int ncol = s_start[Hlat];
    if (ncol > MAXCOL) ncol = MAXCOL;

    for (int j = tid; j < ncol; j += 256) {
        int lo = 0, hi2 = Hlat;
        while (lo + 1 < hi2) {
            int mid = (lo + hi2) >> 1;
            if (s_start[mid] <= j) lo = mid; else hi2 = mid;
        }
        int a = s_arcv[lo];
        int w = wo0 - a + (j - s_start[lo]);
        s_off[j] = lo * 256 + (w & 255);
        s_aux[j] = (a << 8) | ((w - wo0) & 255);
    }
    __syncthreads();

    // --- Phase 1: logits. Warp per column; one K load -> 4 dots. ---
    const int tq = lane & 3;   // after transpose-reduce, lane holds sum for t = lane&3
    float4 qa[4], qb[4];
    #pragma unroll
    for (int t = 0; t < 4; ++t) {
        qa[t] = *(const float4*)&s_q[t][lane * 4];
        qb[t] = *(const float4*)&s_q[t][128 + lane * 4];
    }
    const float* kb = g_k + (size_t)b * HWsz * Cdim;
    bool b1 = (lane & 1), b2 = (lane & 2);
    float lmax = -INFINITY;

    #pragma unroll 2
    for (int j = warp; j < ncol; j += 8) {
        const float* kr = kb + (size_t)s_off[j] * Cdim;
        float4 k0 = *(const float4*)(kr + lane * 4);
        float4 k1 = *(const float4*)(kr + 128 + lane * 4);
        float p[4];
        #pragma unroll
        for (int t = 0; t < 4; ++t) {
            float s = k0.x * qa[t].x;
            s = fmaf(k0.y, qa[t].y, s); s = fmaf(k0.z, qa[t].z, s); s = fmaf(k0.w, qa[t].w, s);
            s = fmaf(k1.x, qb[t].x, s); s = fmaf(k1.y, qb[t].y, s);
            s = fmaf(k1.z, qb[t].z, s); s = fmaf(k1.w, qb[t].w, s);
            p[t] = s;
        }
        // transpose-reduce: lane ends with full sum for t = lane&3
        float uA = b1 ? p[1] : p[0], wA = b1 ? p[0] : p[1];
        uA += __shfl_xor_sync(0xffffffffu, wA, 1);
        float uB = b1 ? p[3] : p[2], wB = b1 ? p[2] : p[3];
        uB += __shfl_xor_sync(0xffffffffu, wB, 1);
        float v = b2 ? uB : uA, xx = b2 ? uA : uB;
        v += __shfl_xor_sync(0xffffffffu, xx, 2);
        v += __shfl_xor_sync(0xffffffffu, v, 4);
        v += __shfl_xor_sync(0xffffffffu, v, 8);
        v += __shfl_xor_sync(0xffffffffu, v, 16);
        // validity mask for (t = tq)
        int aux = s_aux[j];
        int a = aux >> 8;
        int dw = ((aux & 255) - tq) & 255;
        bool valid = (dw <= a) || (dw >= 256 - a);
        v = valid ? v : -1e30f;
        if (lane < 4) s_alpha[j * 4 + lane] = v;
        lmax = fmaxf(lmax, v);
    }
    if (lane < 4) s_red[warp * 4 + lane] = lmax;
    __syncthreads();
    if (tid < 4) {
        float m = s_red[tid];
        #pragma unroll
        for (int w = 1; w < 8; ++w) m = fmaxf(m, s_red[w * 4 + tid]);
        s_m[tid] = m;
    }
    __syncthreads();

    // --- Phase 2: alpha + denom (per t = tid&3) ---
    float mt = s_m[tid & 3];
    float dloc = 0.f;
    for (int idx = tid; idx < ncol * 4; idx += 256) {
        int j = idx >> 2;
        float a = __expf(s_alpha[idx] - mt) * qw_lat[s_off[j] >> 8];
        s_alpha[idx] = a;
        dloc += a;
    }
    dloc += __shfl_xor_sync(0xffffffffu, dloc, 4);
    dloc += __shfl_xor_sync(0xffffffffu, dloc, 8);
    dloc += __shfl_xor_sync(0xffffffffu, dloc, 16);
    if (lane < 4) s_red[warp * 4 + lane] = dloc;
    __syncthreads();
    if (tid < 32) {
        float v = s_red[tid];
        v += __shfl_xor_sync(0xffffffffu, v, 4);
        v += __shfl_xor_sync(0xffffffffu, v, 8);
        v += __shfl_xor_sync(0xffffffffu, v, 16);
        if (tid < 4) s_inv[tid] = 1.0f / v;
    }
    __syncthreads();

    // --- Phase 3: V accumulation. One V load -> 4 accumulators. ---
    int g = tid >> 6;
    int c4 = (tid & 63) * 4;
    const float* vb = g_v + (size_t)b * HWsz * Cdim + c4;
    float4 A0 = {0,0,0,0}, A1 = {0,0,0,0}, A2 = {0,0,0,0}, A3 = {0,0,0,0};
    #pragma unroll 2
    for (int j = g; j < ncol; j += 4) {
        float4 al = *(const float4*)&s_alpha[j * 4];
        const float4 vv = *(const float4*)(vb + (size_t)s_off[j] * Cdim);
        A0.x = fmaf(al.x, vv.x, A0.x); A0.y = fmaf(al.x, vv.y, A0.y);
        A0.z = fmaf(al.x, vv.z, A0.z); A0.w = fmaf(al.x, vv.w, A0.w);
        A1.x = fmaf(al.y, vv.x, A1.x); A1.y = fmaf(al.y, vv.y, A1.y);
        A1.z = fmaf(al.y, vv.z, A1.z); A1.w = fmaf(al.y, vv.w, A1.w);
        A2.x = fmaf(al.z, vv.x, A2.x); A2.y = fmaf(al.z, vv.y, A2.y);
        A2.z = fmaf(al.z, vv.z, A2.z); A2.w = fmaf(al.z, vv.w, A2.w);
        A3.x = fmaf(al.w, vv.x, A3.x); A3.y = fmaf(al.w, vv.y, A3.y);
        A3.z = fmaf(al.w, vv.z, A3.z); A3.w = fmaf(al.w, vv.w, A3.w);
    }
    __syncthreads();   // alphas dead; reuse s_alpha for partials [t][g][c]
    float* sp = s_alpha;
    *(float4*)&sp[(0 * 4 + g) * 256 + c4] = A0;
    *(float4*)&sp[(1 * 4 + g) * 256 + c4] = A1;
    *(float4*)&sp[(2 * 4 + g) * 256 + c4] = A2;
    *(float4*)&sp[(3 * 4 + g) * 256 + c4] = A3;
    __syncthreads();

    float4 o;
    {
        float v0 = sp[(0*4+0)*256+tid] + sp[(0*4+1)*256+tid] + sp[(0*4+2)*256+tid] + sp[(0*4+3)*256+tid];
        float v1 = sp[(1*4+0)*256+tid] + sp[(1*4+1)*256+tid] + sp[(1*4+2)*256+tid] + sp[(1*4+3)*256+tid];
        float v2 = sp[(2*4+0)*256+tid] + sp[(2*4+1)*256+tid] + sp[(2*4+2)*256+tid] + sp[(2*4+3)*256+tid];
        float v3 = sp[(3*4+0)*256+tid] + sp[(3*4+1)*256+tid] + sp[(3*4+2)*256+tid] + sp[(3*4+3)*256+tid];
        o.x = v0 * s_inv[0]; o.y = v1 * s_inv[1]; o.z = v2 * s_inv[2]; o.w = v3 * s_inv[3];
    }
    *(float4*)(out + (((size_t)b * Cdim + tid) * Hlat + ho) * Wlon + wo0) = o;
}

// ---------------------------------------------------------------------------
extern "C" void kernel_launch(void* const* d_in, const int* in_sizes, int n_in,
                              void* d_out, int out_size) {
    const float* query = (const float*)d_in[0];
    const float* wq    = (const float*)d_in[1];
    const float* wk    = (const float*)d_in[2];
    const float* wv    = (const float*)d_in[3];
    const float* bq    = (const float*)d_in[4];
    const float* bk    = (const float*)d_in[5];
    const float* bv    = (const float*)d_in[6];
    const float* qw    = (const float*)d_in[7];
    const int*   rows  = (const int*)d_in[8];
    const int*   cols  = (const int*)d_in[9];
    int nnz = in_sizes[8];
    float* out = (float*)d_out;

    zero_cnt_kernel<<<Hlat * Hlat / 256, 256>>>();
    count_kernel<<<(nnz + 255) / 256, 256>>>(rows, cols, nnz);
    arc_kernel<<<Hlat * Hlat / 256, 256>>>();
    qkv_gemm_kernel<<<dim3(HWsz / 128, 6, Bdim), 256>>>(query, wq, wk, wv, bq, bk, bv);
    attn_kernel<<<dim3(Wlon / 4, Hlat, Bdim), 256>>>(qw, out);
}

// round 6
// speedup vs baseline: 3.1519x; 1.2435x over previous
#include <cuda_runtime.h>
#include <cuda_bf16.h>
#include <math.h>
#include <stdint.h>

#define Bdim 2
#define Hlat 128
#define Wlon 256
#define Cdim 256
#define HWsz (Hlat*Wlon)
#define MAXCOL 1536

// Scratch (allocation-free rule: __device__ globals)
__device__ float g_q[(size_t)Bdim*HWsz*Cdim];   // (b,h,w,c), pre-scaled by 1/16
__device__ float g_k[(size_t)Bdim*HWsz*Cdim];
__device__ float g_v[(size_t)Bdim*HWsz*Cdim];
__device__ int   g_cnt[Hlat*Hlat];
__device__ int   g_arc[Hlat*Hlat];

// ---------------------------------------------------------------------------
// Family-portable tensor-core helpers (sm_80 baseline: ldmatrix + mma.sync)
// ---------------------------------------------------------------------------
__device__ __forceinline__ uint32_t smem_u32(const void* p) {
    uint32_t a;
    asm("{ .reg .u64 t; cvta.to.shared.u64 t, %1; cvt.u32.u64 %0, t; }" : "=r"(a) : "l"(p));
    return a;
}
__device__ __forceinline__ void ldsm_x4(uint32_t* r, uint32_t addr) {
    asm volatile("ldmatrix.sync.aligned.m8n8.x4.shared.b16 {%0,%1,%2,%3}, [%4];"
        : "=r"(r[0]), "=r"(r[1]), "=r"(r[2]), "=r"(r[3]) : "r"(addr));
}
__device__ __forceinline__ void ldsm_x4t(uint32_t* r, uint32_t addr) {
    asm volatile("ldmatrix.sync.aligned.m8n8.x4.trans.shared.b16 {%0,%1,%2,%3}, [%4];"
        : "=r"(r[0]), "=r"(r[1]), "=r"(r[2]), "=r"(r[3]) : "r"(addr));
}
__device__ __forceinline__ void mma_bf(float* d, const uint32_t* a, uint32_t b0, uint32_t b1) {
    asm volatile(
        "mma.sync.aligned.m16n8k16.row.col.f32.bf16.bf16.f32 "
        "{%0,%1,%2,%3}, {%4,%5,%6,%7}, {%8,%9}, {%0,%1,%2,%3};"
        : "+f"(d[0]), "+f"(d[1]), "+f"(d[2]), "+f"(d[3])
        : "r"(a[0]), "r"(a[1]), "r"(a[2]), "r"(a[3]), "r"(b0), "r"(b1));
}
// pack two floats into bf16x2 (low half = first arg)
__device__ __forceinline__ uint32_t packbf(float lo, float hi) {
    uint32_t r;
    asm("cvt.rn.bf16x2.f32 %0, %1, %2;" : "=r"(r) : "f"(hi), "f"(lo));
    return r;
}
__device__ __forceinline__ float bflo_f(uint32_t h) { return __uint_as_float(h << 16); }
__device__ __forceinline__ float bfhi_f(uint32_t h) { return __uint_as_float(h & 0xffff0000u); }

// ---------------------------------------------------------------------------
// Arc table precompute (exact, derived from CSR counts)
// ---------------------------------------------------------------------------
__global__ void zero_cnt_kernel() {
    g_cnt[blockIdx.x * 256 + threadIdx.x] = 0;
}
__global__ void count_kernel(const int* __restrict__ rows, const int* __restrict__ cols, int nnz) {
    int i = blockIdx.x * 256 + threadIdx.x;
    if (i >= nnz) return;
    atomicAdd(&g_cnt[rows[i] * Hlat + (cols[i] >> 8)], 1);
}
__global__ void arc_kernel() {
    int i = blockIdx.x * 256 + threadIdx.x;
    int c = g_cnt[i];
    g_arc[i] = (c == 0) ? -1 : ((c >= 256) ? 128 : ((c - 1) >> 1));
}

// ---------------------------------------------------------------------------
// QKV projection via mma.sync bf16 with hi/lo split (3 terms).
// Block: 128 p (M) x 128 j (N), one matrix (mat = blockIdx.y>>1).
// 8 warps = 4 (p) x 2 (j); warp tile 32p x 64j. K chunked by 32.
// ---------------------------------------------------------------------------
__global__ __launch_bounds__(256) void qkv_mma_kernel(
    const float* __restrict__ x,
    const float* __restrict__ wq, const float* __restrict__ wk, const float* __restrict__ wv,
    const float* __restrict__ bq, const float* __restrict__ bk, const float* __restrict__ bv)
{
    // A (x) tile: 32 c-rows x 128 p, padded to 136 elem (272B rows, conflict-free ldmatrix)
    // W tile: 128 j-rows x 32 c, padded to 40 elem (80B rows, conflict-free ldmatrix)
    __shared__ __align__(16) unsigned short A_hi[32][136];
    __shared__ __align__(16) unsigned short A_lo[32][136];
    __shared__ __align__(16) unsigned short W_hi[128][40];
    __shared__ __align__(16) unsigned short W_lo[128][40];

    int tid = threadIdx.x, lane = tid & 31, warp = tid >> 5;
    int p0 = blockIdx.x * 128;
    int nb = blockIdx.y;
    int b  = blockIdx.z;
    int mat = nb >> 1;
    int j0 = (nb & 1) * 128;

    const float* Wm   = (mat == 0) ? wq : (mat == 1) ? wk : wv;
    const float* Bias = (mat == 0) ? bq : (mat == 1) ? bk : bv;
    float*       Out  = (mat == 0) ? g_q : (mat == 1) ? g_k : g_v;
    float osc = (mat == 0) ? 0.0625f : 1.0f;

    const float* xb = x + (size_t)b * Cdim * HWsz;

    uint32_t a_hi_base = smem_u32(A_hi);
    uint32_t a_lo_base = smem_u32(A_lo);
    uint32_t w_hi_base = smem_u32(W_hi);
    uint32_t w_lo_base = smem_u32(W_lo);

    float acc[2][8][4];
    #pragma unroll
    for (int i = 0; i < 2; ++i)
        #pragma unroll
        for (int j = 0; j < 8; ++j)
            #pragma unroll
            for (int k = 0; k < 4; ++k) acc[i][j][k] = 0.f;

    int wp = warp & 3, wj = warp >> 2;
    int g  = lane >> 3, jl = lane & 7;
    // ldmatrix lane-address components
    int a_krow = jl + ((g & 2) ? 8 : 0);
    int a_mcol = (g & 1) ? 8 : 0;
    int b_nrow = jl + ((g & 2) ? 8 : 0);
    int b_kcol = (g & 1) ? 8 : 0;

    for (int chunk = 0; chunk < 8; ++chunk) {
        int c0 = chunk * 32;

        // ---- stage x tile (32c x 128p) as bf16 hi/lo ----
        #pragma unroll
        for (int it = 0; it < 4; ++it) {
            int idx = tid + it * 256;          // 0..1023
            int r = idx >> 5, c4 = idx & 31;   // c row, p float4-group
            float4 v = *(const float4*)(xb + (size_t)(c0 + r) * HWsz + p0 + c4 * 4);
            uint32_t h0 = packbf(v.x, v.y), h1 = packbf(v.z, v.w);
            float lx = v.x - bflo_f(h0), ly = v.y - bfhi_f(h0);
            float lz = v.z - bflo_f(h1), lw = v.w - bfhi_f(h1);
            uint32_t l0 = packbf(lx, ly), l1 = packbf(lz, lw);
            *(uint2*)&A_hi[r][c4 * 4] = make_uint2(h0, h1);
            *(uint2*)&A_lo[r][c4 * 4] = make_uint2(l0, l1);
        }
        // ---- stage W tile (128j x 32c) as bf16 hi/lo ----
        #pragma unroll
        for (int it = 0; it < 4; ++it) {
            int idx = tid + it * 256;          // 0..1023
            int j = idx >> 3, f4 = idx & 7;    // j row, c float4-group
            float4 v = *(const float4*)(Wm + (size_t)(j0 + j) * Cdim + c0 + f4 * 4);
            uint32_t h0 = packbf(v.x, v.y), h1 = packbf(v.z, v.w);
            float lx = v.x - bflo_f(h0), ly = v.y - bfhi_f(h0);
            float lz = v.z - bflo_f(h1), lw = v.w - bfhi_f(h1);
            uint32_t l0 = packbf(lx, ly), l1 = packbf(lz, lw);
            *(uint2*)&W_hi[j][f4 * 4] = make_uint2(h0, h1);
            *(uint2*)&W_lo[j][f4 * 4] = make_uint2(l0, l1);
        }
        __syncthreads();

        // ---- compute: 2 k16-steps per chunk ----
        #pragma unroll
        for (int ks = 0; ks < 2; ++ks) {
            int k0 = ks * 16;
            uint32_t ah[2][4], al[2][4];
            #pragma unroll
            for (int mt = 0; mt < 2; ++mt) {
                int m0 = wp * 32 + mt * 16;
                uint32_t off = (uint32_t)((k0 + a_krow) * 272 + (m0 + a_mcol) * 2);
                ldsm_x4t(ah[mt], a_hi_base + off);
                ldsm_x4t(al[mt], a_lo_base + off);
            }
            #pragma unroll
            for (int np = 0; np < 4; ++np) {
                int n0 = wj * 64 + np * 16;
                uint32_t off = (uint32_t)((n0 + b_nrow) * 80 + (k0 + b_kcol) * 2);
                uint32_t bh[4], bl[4];
                ldsm_x4(bh, w_hi_base + off);
                ldsm_x4(bl, w_lo_base + off);
                #pragma unroll
                for (int mt = 0; mt < 2; ++mt) {
                    mma_bf(acc[mt][np * 2],     ah[mt], bh[0], bh[1]);
                    mma_bf(acc[mt][np * 2],     al[mt], bh[0], bh[1]);
                    mma_bf(acc[mt][np * 2],     ah[mt], bl[0], bl[1]);
                    mma_bf(acc[mt][np * 2 + 1], ah[mt], bh[2], bh[3]);
                    mma_bf(acc[mt][np * 2 + 1], al[mt], bh[2], bh[3]);
                    mma_bf(acc[mt][np * 2 + 1], ah[mt], bl[2], bl[3]);
                }
            }
        }
        __syncthreads();
    }

    // ---- epilogue: scale + bias, store (p, j) ----
    float* opb = Out + (size_t)b * HWsz * Cdim;
    int r0 = lane >> 2, cp = (lane & 3) * 2;
    #pragma unroll
    for (int mt = 0; mt < 2; ++mt) {
        int p = p0 + wp * 32 + mt * 16 + r0;
        #pragma unroll
        for (int nt = 0; nt < 8; ++nt) {
            int jc = j0 + wj * 64 + nt * 8 + cp;
            float b0v = Bias[jc], b1v = Bias[jc + 1];
            float2 s0, s1;
            s0.x = fmaf(acc[mt][nt][0], osc, b0v);
            s0.y = fmaf(acc[mt][nt][1], osc, b1v);
            s1.x = fmaf(acc[mt][nt][2], osc, b0v);
            s1.y = fmaf(acc[mt][nt][3], osc, b1v);
            *(float2*)(opb + (size_t)p * Cdim + jc) = s0;
            *(float2*)(opb + (size_t)(p + 8) * Cdim + jc) = s1;
        }
    }
}

// ---------------------------------------------------------------------------
// Attention over distinct columns (unchanged from round 4 — passing config).
// ---------------------------------------------------------------------------
__global__ __launch_bounds__(256) void attn_kernel(
    const float* __restrict__ qw_lat,
    float* __restrict__ out)
{
    __shared__ __align__(16) float s_q[4][Cdim];
    __shared__ __align__(16) float s_alpha[MAXCOL * 4];
    __shared__ __align__(16) int   s_off[MAXCOL];
    __shared__ __align__(16) int   s_aux[MAXCOL];
    __shared__ int   s_arcv[Hlat];
    __shared__ int   s_wid[Hlat];
    __shared__ int   s_start[Hlat + 1];
    __shared__ float s_red[32];
    __shared__ float s_m[4];
    __shared__ float s_inv[4];

    int wo0 = blockIdx.x * 4;
    int ho = blockIdx.y, b = blockIdx.z;
    int tid = threadIdx.x, lane = tid & 31, warp = tid >> 5;

    if (tid < Hlat) {
        int a = g_arc[ho * Hlat + tid];
        s_arcv[tid] = a;
        int w = (a < 0) ? 0 : (2 * a + 4);
        s_wid[tid] = (w > 256) ? 256 : w;
    }
    {
        int t = tid >> 6; int c4 = (tid & 63) * 4;
        *(float4*)&s_q[t][c4] =
            *(const float4*)(g_q + (((size_t)b * Hlat + ho) * Wlon + wo0 + t) * Cdim + c4);
    }
    __syncthreads();

    if (warp == 0) {
        int b0 = lane * 4;
        int w0 = s_wid[b0], w1 = s_wid[b0 + 1], w2 = s_wid[b0 + 2], w3 = s_wid[b0 + 3];
        int p1 = w0 + w1, p2 = p1 + w2, tot = p2 + w3;
        int inc = tot;
        #pragma unroll
        for (int o = 1; o < 32; o <<= 1) {
            int nv = __shfl_up_sync(0xffffffffu, inc, o);
            if (lane >= o) inc += nv;
        }
        int base = inc - tot;
        s_start[b0] = base; s_start[b0 + 1] = base + w0;
        s_start[b0 + 2] = base + p1; s_start[b0 + 3] = base + p2;
        if (lane == 31) s_start[Hlat] = inc;
    }
    __syncthreads();
    int ncol = s_start[Hlat];
    if (ncol > MAXCOL) ncol = MAXCOL;

    for (int j = tid; j < ncol; j += 256) {
        int lo = 0, hi2 = Hlat;
        while (lo + 1 < hi2) {
            int mid = (lo + hi2) >> 1;
            if (s_start[mid] <= j) lo = mid; else hi2 = mid;
        }
        int a = s_arcv[lo];
        int w = wo0 - a + (j - s_start[lo]);
        s_off[j] = lo * 256 + (w & 255);
        s_aux[j] = (a << 8) | ((w - wo0) & 255);
    }
    __syncthreads();

    const int tq = lane & 3;
    float4 qa[4], qb[4];
    #pragma unroll
    for (int t = 0; t < 4; ++t) {
        qa[t] = *(const float4*)&s_q[t][lane * 4];
        qb[t] = *(const float4*)&s_q[t][128 + lane * 4];
    }
    const float* kb = g_k + (size_t)b * HWsz * Cdim;
    bool b1 = (lane & 1), b2 = (lane & 2);
    float lmax = -INFINITY;

    #pragma unroll 2
    for (int j = warp; j < ncol; j += 8) {
        const float* kr = kb + (size_t)s_off[j] * Cdim;
        float4 k0 = *(const float4*)(kr + lane * 4);
        float4 k1 = *(const float4*)(kr + 128 + lane * 4);
        float p[4];
        #pragma unroll
        for (int t = 0; t < 4; ++t) {
            float s = k0.x * qa[t].x;
            s = fmaf(k0.y, qa[t].y, s); s = fmaf(k0.z, qa[t].z, s); s = fmaf(k0.w, qa[t].w, s);
            s = fmaf(k1.x, qb[t].x, s); s = fmaf(k1.y, qb[t].y, s);
            s = fmaf(k1.z, qb[t].z, s); s = fmaf(k1.w, qb[t].w, s);
            p[t] = s;
        }
        float uA = b1 ? p[1] : p[0], wA = b1 ? p[0] : p[1];
        uA += __shfl_xor_sync(0xffffffffu, wA, 1);
        float uB = b1 ? p[3] : p[2], wB = b1 ? p[2] : p[3];
        uB += __shfl_xor_sync(0xffffffffu, wB, 1);
        float v = b2 ? uB : uA, xx = b2 ? uA : uB;
        v += __shfl_xor_sync(0xffffffffu, xx, 2);
        v += __shfl_xor_sync(0xffffffffu, v, 4);
        v += __shfl_xor_sync(0xffffffffu, v, 8);
        v += __shfl_xor_sync(0xffffffffu, v, 16);
        int aux = s_aux[j];
        int a = aux >> 8;
        int dw = ((aux & 255) - tq) & 255;
        bool valid = (dw <= a) || (dw >= 256 - a);
        v = valid ? v : -1e30f;
        if (lane < 4) s_alpha[j * 4 + lane] = v;
        lmax = fmaxf(lmax, v);
    }
    if (lane < 4) s_red[warp * 4 + lane] = lmax;
    __syncthreads();
    if (tid < 4) {
        float m = s_red[tid];
        #pragma unroll
        for (int w = 1; w < 8; ++w) m = fmaxf(m, s_red[w * 4 + tid]);
        s_m[tid] = m;
    }
    __syncthreads();

    float mt = s_m[tid & 3];
    float dloc = 0.f;
    for (int idx = tid; idx < ncol * 4; idx += 256) {
        int j = idx >> 2;
        float a = __expf(s_alpha[idx] - mt) * qw_lat[s_off[j] >> 8];
        s_alpha[idx] = a;
        dloc += a;
    }
    dloc += __shfl_xor_sync(0xffffffffu, dloc, 4);
    dloc += __shfl_xor_sync(0xffffffffu, dloc, 8);
    dloc += __shfl_xor_sync(0xffffffffu, dloc, 16);
    if (lane < 4) s_red[warp * 4 + lane] = dloc;
    __syncthreads();
    if (tid < 32) {
        float v = s_red[tid];
        v += __shfl_xor_sync(0xffffffffu, v, 4);
        v += __shfl_xor_sync(0xffffffffu, v, 8);
        v += __shfl_xor_sync(0xffffffffu, v, 16);
        if (tid < 4) s_inv[tid] = 1.0f / v;
    }
    __syncthreads();

    int g = tid >> 6;
    int c4 = (tid & 63) * 4;
    const float* vb = g_v + (size_t)b * HWsz * Cdim + c4;
    float4 A0 = {0,0,0,0}, A1 = {0,0,0,0}, A2 = {0,0,0,0}, A3 = {0,0,0,0};
    #pragma unroll 2
    for (int j = g; j < ncol; j += 4) {
        float4 al = *(const float4*)&s_alpha[j * 4];
        const float4 vv = *(const float4*)(vb + (size_t)s_off[j] * Cdim);
        A0.x = fmaf(al.x, vv.x, A0.x); A0.y = fmaf(al.x, vv.y, A0.y);
        A0.z = fmaf(al.x, vv.z, A0.z); A0.w = fmaf(al.x, vv.w, A0.w);
        A1.x = fmaf(al.y, vv.x, A1.x); A1.y = fmaf(al.y, vv.y, A1.y);
        A1.z = fmaf(al.y, vv.z, A1.z); A1.w = fmaf(al.y, vv.w, A1.w);
        A2.x = fmaf(al.z, vv.x, A2.x); A2.y = fmaf(al.z, vv.y, A2.y);
        A2.z = fmaf(al.z, vv.z, A2.z); A2.w = fmaf(al.z, vv.w, A2.w);
        A3.x = fmaf(al.w, vv.x, A3.x); A3.y = fmaf(al.w, vv.y, A3.y);
        A3.z = fmaf(al.w, vv.z, A3.z); A3.w = fmaf(al.w, vv.w, A3.w);
    }
    __syncthreads();
    float* sp = s_alpha;
    *(float4*)&sp[(0 * 4 + g) * 256 + c4] = A0;
    *(float4*)&sp[(1 * 4 + g) * 256 + c4] = A1;
    *(float4*)&sp[(2 * 4 + g) * 256 + c4] = A2;
    *(float4*)&sp[(3 * 4 + g) * 256 + c4] = A3;
    __syncthreads();

    float4 o;
    {
        float v0 = sp[(0*4+0)*256+tid] + sp[(0*4+1)*256+tid] + sp[(0*4+2)*256+tid] + sp[(0*4+3)*256+tid];
        float v1 = sp[(1*4+0)*256+tid] + sp[(1*4+1)*256+tid] + sp[(1*4+2)*256+tid] + sp[(1*4+3)*256+tid];
        float v2 = sp[(2*4+0)*256+tid] + sp[(2*4+1)*256+tid] + sp[(2*4+2)*256+tid] + sp[(2*4+3)*256+tid];
        float v3 = sp[(3*4+0)*256+tid] + sp[(3*4+1)*256+tid] + sp[(3*4+2)*256+tid] + sp[(3*4+3)*256+tid];
        o.x = v0 * s_inv[0]; o.y = v1 * s_inv[1]; o.z = v2 * s_inv[2]; o.w = v3 * s_inv[3];
    }
    *(float4*)(out + (((size_t)b * Cdim + tid) * Hlat + ho) * Wlon + wo0) = o;
}

// ---------------------------------------------------------------------------
extern "C" void kernel_launch(void* const* d_in, const int* in_sizes, int n_in,
                              void* d_out, int out_size) {
    const float* query = (const float*)d_in[0];
    const float* wq    = (const float*)d_in[1];
    const float* wk    = (const float*)d_in[2];
    const float* wv    = (const float*)d_in[3];
    const float* bq    = (const float*)d_in[4];
    const float* bk    = (const float*)d_in[5];
    const float* bv    = (const float*)d_in[6];
    const float* qw    = (const float*)d_in[7];
    const int*   rows  = (const int*)d_in[8];
    const int*   cols  = (const int*)d_in[9];
    int nnz = in_sizes[8];
    float* out = (float*)d_out;

    zero_cnt_kernel<<<Hlat * Hlat / 256, 256>>>();
    count_kernel<<<(nnz + 255) / 256, 256>>>(rows, cols, nnz);
    arc_kernel<<<Hlat * Hlat / 256, 256>>>();
    qkv_mma_kernel<<<dim3(HWsz / 128, 6, Bdim), 256>>>(query, wq, wk, wv, bq, bk, bv);
    attn_kernel<<<dim3(Wlon / 4, Hlat, Bdim), 256>>>(qw, out);
}